// round 6
// baseline (speedup 1.0000x reference)
#include <cuda_runtime.h>
#include <cuda_bf16.h>
#include <math.h>
#include <stdint.h>

#define NVAR 30000
#define NCLS 60000
#define DIM 256
#define NHEAD 8

// ---------------- scratch layout (float units) ----------------
#define OFF_PV     0ull            // 30000*768 fp32 packed [q|k|v]
#define OFF_PC     23040000ull     // 60000*768 fp32
#define OFF_NUMVP  69120000ull
#define OFF_NUMVN  76800000ull
#define OFF_NUMCP  84480000ull
#define OFF_NUMCN  99840000ull
#define OFF_DENVP  115200000ull
#define OFF_DENVN  115440000ull
#define OFF_DENCP  115680000ull
#define OFF_DENCN  116160000ull
#define OFF_V1     116640000ull    // 30000*256 fp32
#define OFF_C1     124320000ull    // 60000*256 fp32
#define OFF_TMP    139680000ull    // 60000*256 fp32
#define OFF_BF     155040000ull    // bf16 area (float units)
// bf16-element offsets within BF area:
#define B_VBF   0ull               // 30000*256
#define B_CBF   7680000ull         // 60000*256
#define B_V1B   23040000ull        // 30000*256
#define B_C1B   30720000ull        // 60000*256
#define B_HID   46080000ull        // 60000*256
#define B_WQKV  61440000ull        // 256*768
#define B_FVW1  61636608ull        // 65536
#define B_FVW2  61702144ull
#define B_FCW1  61767680ull
#define B_FCW2  61833216ull
// bf16 total 61,898,752 -> 30,949,376 floats
#define OFF_B768   185989376ull    // 768 floats
#define SCRATCH_TOTAL 185990400ull

__device__ float g_scratch[SCRATCH_TOTAL];

// ---------------- helpers ----------------
__device__ __forceinline__ void ldsm_x4(uint32_t* r, uint32_t saddr) {
    asm volatile("ldmatrix.sync.aligned.m8n8.x4.shared.b16 {%0,%1,%2,%3}, [%4];"
                 : "=r"(r[0]), "=r"(r[1]), "=r"(r[2]), "=r"(r[3]) : "r"(saddr));
}
__device__ __forceinline__ void ldsm_x4_trans(uint32_t* r, uint32_t saddr) {
    asm volatile("ldmatrix.sync.aligned.m8n8.x4.trans.shared.b16 {%0,%1,%2,%3}, [%4];"
                 : "=r"(r[0]), "=r"(r[1]), "=r"(r[2]), "=r"(r[3]) : "r"(saddr));
}
__device__ __forceinline__ void mma_bf16(float* d, const uint32_t* a, const uint32_t* b) {
    asm volatile(
        "mma.sync.aligned.m16n8k16.row.col.f32.bf16.bf16.f32 "
        "{%0,%1,%2,%3}, {%4,%5,%6,%7}, {%8,%9}, {%0,%1,%2,%3};"
        : "+f"(d[0]), "+f"(d[1]), "+f"(d[2]), "+f"(d[3])
        : "r"(a[0]), "r"(a[1]), "r"(a[2]), "r"(a[3]),
          "r"(b[0]), "r"(b[1]));
}
__device__ __forceinline__ void red_add_v4(float* addr, float4 v) {
    asm volatile("red.global.add.v4.f32 [%0], {%1,%2,%3,%4};"
                 :: "l"(addr), "f"(v.x), "f"(v.y), "f"(v.z), "f"(v.w) : "memory");
}

// ---------------- conversion kernels ----------------
__global__ void cvt_f2b4(const float* __restrict__ s, __nv_bfloat16* __restrict__ d, int n4) {
    int i = blockIdx.x * blockDim.x + threadIdx.x;
    if (i >= n4) return;
    float4 t = ((const float4*)s)[i];
    __nv_bfloat162 lo = __float22bfloat162_rn(make_float2(t.x, t.y));
    __nv_bfloat162 hi = __float22bfloat162_rn(make_float2(t.z, t.w));
    ((uint2*)d)[i] = make_uint2(*(uint32_t*)&lo, *(uint32_t*)&hi);
}
__global__ void build_wqkv(const float* __restrict__ Wq, const float* __restrict__ Wkv,
                           __nv_bfloat16* __restrict__ dst) {
    int i = blockIdx.x * blockDim.x + threadIdx.x;
    if (i >= 256 * 768) return;
    int k = i / 768, j = i % 768;
    float val = (j < 256) ? Wq[k * 256 + j] : Wkv[k * 512 + (j - 256)];
    dst[i] = __float2bfloat16(val);
}
__global__ void build_bias768(const float* __restrict__ bq, const float* __restrict__ bkv,
                              float* __restrict__ dst) {
    int j = blockIdx.x * blockDim.x + threadIdx.x;
    if (j < 768) dst[j] = (j < 256) ? bq[j] : bkv[j - 256];
}

// ---------------- bf16 tensor-core GEMM ----------------
// C[N,M](fp32) / Cb[N,M](bf16) = A[N,256](bf16,lda) @ W[256,M](bf16) + bias (+GELU)
#define BM 128
#define BN 64
#define BK 32
#define ASTR 40
#define BSTR 72

__global__ __launch_bounds__(256) void tgemm_bf(
    const __nv_bfloat16* __restrict__ A, int lda,
    const __nv_bfloat16* __restrict__ W,
    const float* __restrict__ bias,
    float* __restrict__ C, __nv_bfloat16* __restrict__ Cb,
    int N, int M, int gelu)
{
    __shared__ __nv_bfloat16 As[BM * ASTR];
    __shared__ __nv_bfloat16 Ws[BK * BSTR];

    int tid = threadIdx.x;
    int lane = tid & 31;
    int warp = tid >> 5;
    int wm = (warp & 3) * 32;
    int wn = (warp >> 2) * 32;
    int bm = blockIdx.y * BM;
    int bn = blockIdx.x * BN;

    uint32_t as_base = (uint32_t)__cvta_generic_to_shared(As);
    uint32_t ws_base = (uint32_t)__cvta_generic_to_shared(Ws);

    // A: 512 granules of 8 bf16 (16B); 2 per thread
    int a_row[2], a_col[2];
    #pragma unroll
    for (int i = 0; i < 2; i++) {
        int g = tid * 2 + i;
        a_row[i] = g >> 2;
        a_col[i] = (g & 3) * 8;
    }
    // W: 256 granules; 1 per thread
    int w_row = tid >> 3;
    int w_col = (tid & 7) * 8;

    uint4 pa[2], pb;
    const uint4 zero4 = make_uint4(0, 0, 0, 0);

    float acc[2][4][4];
    #pragma unroll
    for (int mt = 0; mt < 2; mt++)
        #pragma unroll
        for (int nt = 0; nt < 4; nt++)
            #pragma unroll
            for (int i = 0; i < 4; i++) acc[mt][nt][i] = 0.0f;

    int a_r = lane & 15;
    int a_c = (lane >> 4) * 8;

    // ---- load slab 0 ----
    #pragma unroll
    for (int i = 0; i < 2; i++) {
        int gr = bm + a_row[i];
        pa[i] = (gr < N) ? *(const uint4*)&A[(size_t)gr * lda + a_col[i]] : zero4;
    }
    pb = *(const uint4*)&W[(size_t)w_row * M + bn + w_col];
    #pragma unroll
    for (int i = 0; i < 2; i++)
        *(uint4*)&As[a_row[i] * ASTR + a_col[i]] = pa[i];
    *(uint4*)&Ws[w_row * BSTR + w_col] = pb;
    __syncthreads();

    for (int s = 0; s < 8; s++) {
        if (s < 7) {
            int k0 = (s + 1) * BK;
            #pragma unroll
            for (int i = 0; i < 2; i++) {
                int gr = bm + a_row[i];
                pa[i] = (gr < N) ? *(const uint4*)&A[(size_t)gr * lda + k0 + a_col[i]] : zero4;
            }
            pb = *(const uint4*)&W[(size_t)(k0 + w_row) * M + bn + w_col];
        }

        #pragma unroll
        for (int ks = 0; ks < 2; ks++) {
            int kb = ks * 16;
            uint32_t af[2][4], bf[2][4];
            #pragma unroll
            for (int mt = 0; mt < 2; mt++) {
                int row = wm + mt * 16 + a_r;
                int col = kb + a_c;
                ldsm_x4(af[mt], as_base + (uint32_t)(row * ASTR + col) * 2);
            }
            #pragma unroll
            for (int p = 0; p < 2; p++) {
                int row = kb + (lane & 15);
                int col = wn + p * 16 + (lane >> 4) * 8;
                ldsm_x4_trans(bf[p], ws_base + (uint32_t)(row * BSTR + col) * 2);
            }
            #pragma unroll
            for (int mt = 0; mt < 2; mt++)
                #pragma unroll
                for (int nt = 0; nt < 4; nt++)
                    mma_bf16(acc[mt][nt], af[mt], &bf[nt >> 1][(nt & 1) * 2]);
        }

        __syncthreads();
        if (s < 7) {
            #pragma unroll
            for (int i = 0; i < 2; i++)
                *(uint4*)&As[a_row[i] * ASTR + a_col[i]] = pa[i];
            *(uint4*)&Ws[w_row * BSTR + w_col] = pb;
            __syncthreads();
        }
    }

    // ---- epilogue ----
    #pragma unroll
    for (int mt = 0; mt < 2; mt++) {
        int r0 = bm + wm + mt * 16 + (lane >> 2);
        #pragma unroll
        for (int nt = 0; nt < 4; nt++) {
            int cb = bn + wn + nt * 8 + (lane & 3) * 2;
            float b0 = bias[cb], b1 = bias[cb + 1];
            float2 lo = make_float2(acc[mt][nt][0] + b0, acc[mt][nt][1] + b1);
            float2 hi = make_float2(acc[mt][nt][2] + b0, acc[mt][nt][3] + b1);
            if (gelu) {
                lo.x = 0.5f * lo.x * (1.0f + erff(lo.x * 0.70710678118654752f));
                lo.y = 0.5f * lo.y * (1.0f + erff(lo.y * 0.70710678118654752f));
                hi.x = 0.5f * hi.x * (1.0f + erff(hi.x * 0.70710678118654752f));
                hi.y = 0.5f * hi.y * (1.0f + erff(hi.y * 0.70710678118654752f));
            }
            if (C) {
                if (r0 < N)     *(float2*)&C[(size_t)r0 * M + cb] = lo;
                if (r0 + 8 < N) *(float2*)&C[(size_t)(r0 + 8) * M + cb] = hi;
            }
            if (Cb) {
                __nv_bfloat162 blo = __float22bfloat162_rn(lo);
                __nv_bfloat162 bhi = __float22bfloat162_rn(hi);
                if (r0 < N)     *(__nv_bfloat162*)&Cb[(size_t)r0 * M + cb] = blo;
                if (r0 + 8 < N) *(__nv_bfloat162*)&Cb[(size_t)(r0 + 8) * M + cb] = bhi;
            }
        }
    }
}

// ---------------- edge attention: packed rows [q|k|v], stride 768 ----------------
__global__ void edge_attn(
    const float* __restrict__ Pq, const float* __restrict__ Pkv,
    const int* __restrict__ eq, const int* __restrict__ ek,
    int nE, float* __restrict__ num, float* __restrict__ den)
{
    int warp = (int)(((size_t)blockIdx.x * blockDim.x + threadIdx.x) >> 5);
    int lane = threadIdx.x & 31;
    if (warp >= nE) return;
    int s = eq[warp];
    int t = ek[warp];
    const float4* q4 = (const float4*)(Pq + (size_t)s * 768);
    const float4* k4 = (const float4*)(Pkv + (size_t)t * 768 + 256);
    const float4* v4 = (const float4*)(Pkv + (size_t)t * 768 + 512);

    float e[2];
    #pragma unroll
    for (int ch = 0; ch < 2; ch++) {
        float4 qq = q4[ch * 32 + lane];
        float4 kk = k4[ch * 32 + lane];
        float p = qq.x * kk.x + qq.y * kk.y + qq.z * kk.z + qq.w * kk.w;
        p += __shfl_xor_sync(0xffffffffu, p, 1);
        p += __shfl_xor_sync(0xffffffffu, p, 2);
        p += __shfl_xor_sync(0xffffffffu, p, 4);
        e[ch] = __expf(p * 0.17677669529663687f);
    }
    #pragma unroll
    for (int ch = 0; ch < 2; ch++) {
        if ((lane & 7) == 0)
            atomicAdd(&den[(size_t)s * NHEAD + ch * 4 + (lane >> 3)], e[ch]);
        float4 vv = v4[ch * 32 + lane];
        red_add_v4(&num[(size_t)s * 256 + ch * 128 + lane * 4],
                   make_float4(e[ch] * vv.x, e[ch] * vv.y, e[ch] * vv.z, e[ch] * vv.w));
    }
}

// ---------------- y = LN(x + num_p/den_p + num_n/den_n), dual fp32+bf16 out ----------------
__global__ void ln_att(const float* __restrict__ x,
                       const float* __restrict__ np_, const float* __restrict__ dp,
                       const float* __restrict__ nn_, const float* __restrict__ dn,
                       const float* __restrict__ g, const float* __restrict__ b,
                       float* __restrict__ y, __nv_bfloat16* __restrict__ yb, int n)
{
    int row = blockIdx.x * (blockDim.x >> 5) + (threadIdx.x >> 5);
    int lane = threadIdx.x & 31;
    if (row >= n) return;
    float vals[8];
    float s = 0.0f;
    #pragma unroll
    for (int i = 0; i < 8; i++) {
        size_t idx = (size_t)row * 256 + i * 32 + lane;
        float a = x[idx];
        float dpi = dp[(size_t)row * NHEAD + i];
        float dni = dn[(size_t)row * NHEAD + i];
        if (dpi > 0.0f) a += np_[idx] / dpi;
        if (dni > 0.0f) a += nn_[idx] / dni;
        vals[i] = a;
        s += a;
    }
    #pragma unroll
    for (int o = 16; o > 0; o >>= 1) s += __shfl_xor_sync(0xffffffffu, s, o);
    float mean = s * (1.0f / 256.0f);
    float v2 = 0.0f;
    #pragma unroll
    for (int i = 0; i < 8; i++) { float d = vals[i] - mean; v2 += d * d; }
    #pragma unroll
    for (int o = 16; o > 0; o >>= 1) v2 += __shfl_xor_sync(0xffffffffu, v2, o);
    float rstd = rsqrtf(v2 * (1.0f / 256.0f) + 1e-5f);
    #pragma unroll
    for (int i = 0; i < 8; i++) {
        int cidx = i * 32 + lane;
        float out = (vals[i] - mean) * rstd * g[cidx] + b[cidx];
        y[(size_t)row * 256 + cidx] = out;
        yb[(size_t)row * 256 + cidx] = __float2bfloat16(out);
    }
}

// ---------------- y = LN(x + a) ----------------
__global__ void ln_add(const float* __restrict__ x, const float* __restrict__ a,
                       const float* __restrict__ g, const float* __restrict__ b,
                       float* __restrict__ y, int n)
{
    int row = blockIdx.x * (blockDim.x >> 5) + (threadIdx.x >> 5);
    int lane = threadIdx.x & 31;
    if (row >= n) return;
    float vals[8];
    float s = 0.0f;
    #pragma unroll
    for (int i = 0; i < 8; i++) {
        size_t idx = (size_t)row * 256 + i * 32 + lane;
        vals[i] = x[idx] + a[idx];
        s += vals[i];
    }
    #pragma unroll
    for (int o = 16; o > 0; o >>= 1) s += __shfl_xor_sync(0xffffffffu, s, o);
    float mean = s * (1.0f / 256.0f);
    float v2 = 0.0f;
    #pragma unroll
    for (int i = 0; i < 8; i++) { float d = vals[i] - mean; v2 += d * d; }
    #pragma unroll
    for (int o = 16; o > 0; o >>= 1) v2 += __shfl_xor_sync(0xffffffffu, v2, o);
    float rstd = rsqrtf(v2 * (1.0f / 256.0f) + 1e-5f);
    #pragma unroll
    for (int i = 0; i < 8; i++) {
        int cidx = i * 32 + lane;
        y[(size_t)row * 256 + cidx] = (vals[i] - mean) * rstd * g[cidx] + b[cidx];
    }
}

static inline void launch_gemm(const __nv_bfloat16* A, int lda, const __nv_bfloat16* W,
                               const float* bias, float* C, __nv_bfloat16* Cb,
                               int N, int M, int gelu) {
    dim3 grid(M / BN, (N + BM - 1) / BM);
    tgemm_bf<<<grid, 256>>>(A, lda, W, bias, C, Cb, N, M, gelu);
}

extern "C" void kernel_launch(void* const* d_in, const int* in_sizes, int n_in,
                              void* d_out, int out_size)
{
    const float* v       = (const float*)d_in[0];
    const float* c       = (const float*)d_in[1];
    const int*   adj_pos = (const int*)d_in[2];
    const int*   adj_neg = (const int*)d_in[3];
    const float* Wq      = (const float*)d_in[4];
    const float* bq      = (const float*)d_in[5];
    const float* Wkv     = (const float*)d_in[6];
    const float* bkv     = (const float*)d_in[7];
    const float* fvw1    = (const float*)d_in[8];
    const float* fvb1    = (const float*)d_in[9];
    const float* fvw2    = (const float*)d_in[10];
    const float* fvb2    = (const float*)d_in[11];
    const float* fcw1    = (const float*)d_in[12];
    const float* fcb1    = (const float*)d_in[13];
    const float* fcw2    = (const float*)d_in[14];
    const float* fcb2    = (const float*)d_in[15];
    const float* lavg    = (const float*)d_in[16];
    const float* lavb    = (const float*)d_in[17];
    const float* lfvg    = (const float*)d_in[18];
    const float* lfvb    = (const float*)d_in[19];
    const float* lacg    = (const float*)d_in[20];
    const float* lacb    = (const float*)d_in[21];
    const float* lfcg    = (const float*)d_in[22];
    const float* lfcb    = (const float*)d_in[23];

    int E = in_sizes[2] / 2;

    float* buf;
    cudaGetSymbolAddress((void**)&buf, g_scratch);

    float* pv    = buf + OFF_PV;
    float* pc    = buf + OFF_PC;
    float* numVp = buf + OFF_NUMVP;
    float* numVn = buf + OFF_NUMVN;
    float* numCp = buf + OFF_NUMCP;
    float* numCn = buf + OFF_NUMCN;
    float* denVp = buf + OFF_DENVP;
    float* denVn = buf + OFF_DENVN;
    float* denCp = buf + OFF_DENCP;
    float* denCn = buf + OFF_DENCN;
    float* v1    = buf + OFF_V1;
    float* c1    = buf + OFF_C1;
    float* tmp   = buf + OFF_TMP;
    float* b768  = buf + OFF_B768;

    __nv_bfloat16* bfb   = (__nv_bfloat16*)(buf + OFF_BF);
    __nv_bfloat16* v_bf  = bfb + B_VBF;
    __nv_bfloat16* c_bf  = bfb + B_CBF;
    __nv_bfloat16* v1b   = bfb + B_V1B;
    __nv_bfloat16* c1b   = bfb + B_C1B;
    __nv_bfloat16* hidb  = bfb + B_HID;
    __nv_bfloat16* wqkvb = bfb + B_WQKV;
    __nv_bfloat16* fvw1b = bfb + B_FVW1;
    __nv_bfloat16* fvw2b = bfb + B_FVW2;
    __nv_bfloat16* fcw1b = bfb + B_FCW1;
    __nv_bfloat16* fcw2b = bfb + B_FCW2;

    float* out_v = (float*)d_out;
    float* out_c = out_v + (size_t)NVAR * DIM;

    // ---- conversions (once per launch) ----
    cvt_f2b4<<<(NVAR * 256 / 4 + 255) / 256, 256>>>(v, v_bf, NVAR * 256 / 4);
    cvt_f2b4<<<(NCLS * 256 / 4 + 255) / 256, 256>>>(c, c_bf, NCLS * 256 / 4);
    cvt_f2b4<<<(65536 / 4 + 255) / 256, 256>>>(fvw1, fvw1b, 65536 / 4);
    cvt_f2b4<<<(65536 / 4 + 255) / 256, 256>>>(fvw2, fvw2b, 65536 / 4);
    cvt_f2b4<<<(65536 / 4 + 255) / 256, 256>>>(fcw1, fcw1b, 65536 / 4);
    cvt_f2b4<<<(65536 / 4 + 255) / 256, 256>>>(fcw2, fcw2b, 65536 / 4);
    build_wqkv<<<(256 * 768 + 255) / 256, 256>>>(Wq, Wkv, wqkvb);
    build_bias768<<<3, 256>>>(bq, bkv, b768);

    cudaMemsetAsync(numVp, 0, (size_t)(OFF_V1 - OFF_NUMVP) * sizeof(float), 0);

    // ---- fused projections: [q|k|v] ----
    launch_gemm(v_bf, 256, wqkvb, b768, pv, nullptr, NVAR, 768, 0);
    launch_gemm(c_bf, 256, wqkvb, b768, pc, nullptr, NCLS, 768, 0);

    int eblocks = (E * 32 + 255) / 256;

    edge_attn<<<eblocks, 256>>>(pv, pc, adj_pos + E, adj_pos, E, numVp, denVp);
    edge_attn<<<eblocks, 256>>>(pc, pv, adj_pos, adj_pos + E, E, numCp, denCp);
    edge_attn<<<eblocks, 256>>>(pv, pc, adj_neg + E, adj_neg, E, numVn, denVn);
    edge_attn<<<eblocks, 256>>>(pc, pv, adj_neg, adj_neg + E, E, numCn, denCn);

    ln_att<<<(NVAR + 7) / 8, 256>>>(v, numVp, denVp, numVn, denVn, lavg, lavb, v1, v1b, NVAR);
    ln_att<<<(NCLS + 7) / 8, 256>>>(c, numCp, denCp, numCn, denCn, lacg, lacb, c1, c1b, NCLS);

    // FFN v
    launch_gemm(v1b, 256, fvw1b, fvb1, nullptr, hidb, NVAR, 256, 1);
    launch_gemm(hidb, 256, fvw2b, fvb2, tmp, nullptr, NVAR, 256, 0);
    ln_add<<<(NVAR + 7) / 8, 256>>>(v1, tmp, lfvg, lfvb, out_v, NVAR);

    // FFN c
    launch_gemm(c1b, 256, fcw1b, fcb1, nullptr, hidb, NCLS, 256, 1);
    launch_gemm(hidb, 256, fcw2b, fcb2, tmp, nullptr, NCLS, 256, 0);
    ln_add<<<(NCLS + 7) / 8, 256>>>(c1, tmp, lfcg, lfcb, out_c, NCLS);
}

// round 7
// speedup vs baseline: 1.0557x; 1.0557x over previous
#include <cuda_runtime.h>
#include <cuda_bf16.h>
#include <math.h>
#include <stdint.h>

#define NVAR 30000
#define NCLS 60000
#define DIM 256
#define NHEAD 8

// ---------------- scratch layout (float units) ----------------
#define OFF_PV     0ull            // 30000*768 fp32 (only v-part cols 512..767 written)
#define OFF_PC     23040000ull     // 60000*768 fp32
#define OFF_NUMVP  69120000ull
#define OFF_NUMVN  76800000ull
#define OFF_NUMCP  84480000ull
#define OFF_NUMCN  99840000ull
#define OFF_DENVP  115200000ull
#define OFF_DENVN  115440000ull
#define OFF_DENCP  115680000ull
#define OFF_DENCN  116160000ull
#define OFF_V1     116640000ull    // 30000*256 fp32
#define OFF_C1     124320000ull    // 60000*256 fp32
#define OFF_TMP    139680000ull    // 60000*256 fp32
#define OFF_B768   155040000ull    // 1024 floats
#define OFF_BF     155041024ull    // bf16 area
// bf16-element offsets within BF area:
#define B_VBF   0ull               // 30000*256
#define B_CBF   7680000ull         // 60000*256
#define B_PVB   23040000ull        // 30000*512  [q|k] bf16
#define B_PCB   38400000ull        // 60000*512
#define B_V1B   69120000ull        // 30000*256
#define B_C1B   76800000ull        // 60000*256
#define B_HID   92160000ull        // 60000*256
#define B_WQKV  107520000ull       // 256*768
#define B_FFNW  107716608ull       // 4*65536
// bf16 total 107,978,752 -> 53,989,376 floats
#define SCRATCH_TOTAL 209030400ull

__device__ float g_scratch[SCRATCH_TOTAL];

// ---------------- helpers ----------------
__device__ __forceinline__ void ldsm_x4(uint32_t* r, uint32_t saddr) {
    asm volatile("ldmatrix.sync.aligned.m8n8.x4.shared.b16 {%0,%1,%2,%3}, [%4];"
                 : "=r"(r[0]), "=r"(r[1]), "=r"(r[2]), "=r"(r[3]) : "r"(saddr));
}
__device__ __forceinline__ void ldsm_x4_trans(uint32_t* r, uint32_t saddr) {
    asm volatile("ldmatrix.sync.aligned.m8n8.x4.trans.shared.b16 {%0,%1,%2,%3}, [%4];"
                 : "=r"(r[0]), "=r"(r[1]), "=r"(r[2]), "=r"(r[3]) : "r"(saddr));
}
__device__ __forceinline__ void mma_bf16(float* d, const uint32_t* a, const uint32_t* b) {
    asm volatile(
        "mma.sync.aligned.m16n8k16.row.col.f32.bf16.bf16.f32 "
        "{%0,%1,%2,%3}, {%4,%5,%6,%7}, {%8,%9}, {%0,%1,%2,%3};"
        : "+f"(d[0]), "+f"(d[1]), "+f"(d[2]), "+f"(d[3])
        : "r"(a[0]), "r"(a[1]), "r"(a[2]), "r"(a[3]),
          "r"(b[0]), "r"(b[1]));
}
__device__ __forceinline__ void red_add_v4(float* addr, float4 v) {
    asm volatile("red.global.add.v4.f32 [%0], {%1,%2,%3,%4};"
                 :: "l"(addr), "f"(v.x), "f"(v.y), "f"(v.z), "f"(v.w) : "memory");
}

// ---------------- conversion kernels ----------------
__global__ void cvt_f2b4(const float* __restrict__ s, __nv_bfloat16* __restrict__ d, int n4) {
    int i = blockIdx.x * blockDim.x + threadIdx.x;
    if (i >= n4) return;
    float4 t = ((const float4*)s)[i];
    __nv_bfloat162 lo = __float22bfloat162_rn(make_float2(t.x, t.y));
    __nv_bfloat162 hi = __float22bfloat162_rn(make_float2(t.z, t.w));
    ((uint2*)d)[i] = make_uint2(*(uint32_t*)&lo, *(uint32_t*)&hi);
}
// 4 FFN weights (each 65536 floats) in one launch
__global__ void cvt_w4(const float* __restrict__ w1, const float* __restrict__ w2,
                       const float* __restrict__ w3, const float* __restrict__ w4,
                       __nv_bfloat16* __restrict__ dst) {
    int i = blockIdx.x * blockDim.x + threadIdx.x;   // float4 index, 65536 total
    if (i >= 65536) return;
    int which = i >> 14;
    int j = i & 16383;
    const float* src = (which == 0) ? w1 : (which == 1) ? w2 : (which == 2) ? w3 : w4;
    float4 t = ((const float4*)src)[j];
    __nv_bfloat162 lo = __float22bfloat162_rn(make_float2(t.x, t.y));
    __nv_bfloat162 hi = __float22bfloat162_rn(make_float2(t.z, t.w));
    ((uint2*)(dst + (size_t)which * 65536))[j] = make_uint2(*(uint32_t*)&lo, *(uint32_t*)&hi);
}
__global__ void build_wqkv(const float* __restrict__ Wq, const float* __restrict__ Wkv,
                           __nv_bfloat16* __restrict__ dst) {
    int i = blockIdx.x * blockDim.x + threadIdx.x;
    if (i >= 256 * 768) return;
    int k = i / 768, j = i % 768;
    float val = (j < 256) ? Wq[k * 256 + j] : Wkv[k * 512 + (j - 256)];
    dst[i] = __float2bfloat16(val);
}
__global__ void build_bias768(const float* __restrict__ bq, const float* __restrict__ bkv,
                              float* __restrict__ dst) {
    int j = blockIdx.x * blockDim.x + threadIdx.x;
    if (j < 768) dst[j] = (j < 256) ? bq[j] : bkv[j - 256];
}

// ---------------- bf16 tensor-core GEMM, double-buffered smem ----------------
// fp32 C written for cols >= cfrom; bf16 Cb (stride cbs) written for cols < cbto.
#define BM 128
#define BN 64
#define BK 32
#define ASTR 40
#define BSTR 72

__global__ __launch_bounds__(256) void tgemm(
    const __nv_bfloat16* __restrict__ A, int lda,
    const __nv_bfloat16* __restrict__ W,
    const float* __restrict__ bias,
    float* __restrict__ C, int cfrom,
    __nv_bfloat16* __restrict__ Cb, int cbto, int cbs,
    int N, int M, int gelu)
{
    __shared__ __nv_bfloat16 As[2][BM * ASTR];
    __shared__ __nv_bfloat16 Ws[2][BK * BSTR];

    int tid = threadIdx.x;
    int lane = tid & 31;
    int warp = tid >> 5;
    int wm = (warp & 3) * 32;
    int wn = (warp >> 2) * 32;
    int bm = blockIdx.y * BM;
    int bn = blockIdx.x * BN;

    uint32_t as_base = (uint32_t)__cvta_generic_to_shared(&As[0][0]);
    uint32_t ws_base = (uint32_t)__cvta_generic_to_shared(&Ws[0][0]);
    const uint32_t as_sz = BM * ASTR * 2;
    const uint32_t ws_sz = BK * BSTR * 2;

    int a_row[2], a_col[2];
    #pragma unroll
    for (int i = 0; i < 2; i++) {
        int g = tid * 2 + i;
        a_row[i] = g >> 2;
        a_col[i] = (g & 3) * 8;
    }
    int w_row = tid >> 3;
    int w_col = (tid & 7) * 8;

    uint4 pa[2], pb;
    const uint4 zero4 = make_uint4(0, 0, 0, 0);

    float acc[2][4][4];
    #pragma unroll
    for (int mt = 0; mt < 2; mt++)
        #pragma unroll
        for (int nt = 0; nt < 4; nt++)
            #pragma unroll
            for (int i = 0; i < 4; i++) acc[mt][nt][i] = 0.0f;

    int a_r = lane & 15;
    int a_c = (lane >> 4) * 8;

    // ---- slab 0 -> buffer 0 ----
    #pragma unroll
    for (int i = 0; i < 2; i++) {
        int gr = bm + a_row[i];
        pa[i] = (gr < N) ? *(const uint4*)&A[(size_t)gr * lda + a_col[i]] : zero4;
    }
    pb = *(const uint4*)&W[(size_t)w_row * M + bn + w_col];
    #pragma unroll
    for (int i = 0; i < 2; i++)
        *(uint4*)&As[0][a_row[i] * ASTR + a_col[i]] = pa[i];
    *(uint4*)&Ws[0][w_row * BSTR + w_col] = pb;
    __syncthreads();

    for (int s = 0; s < 8; s++) {
        int cur = s & 1, nxt = cur ^ 1;
        if (s < 7) {
            int k0 = (s + 1) * BK;
            #pragma unroll
            for (int i = 0; i < 2; i++) {
                int gr = bm + a_row[i];
                pa[i] = (gr < N) ? *(const uint4*)&A[(size_t)gr * lda + k0 + a_col[i]] : zero4;
            }
            pb = *(const uint4*)&W[(size_t)(k0 + w_row) * M + bn + w_col];
        }

        uint32_t asb = as_base + cur * as_sz;
        uint32_t wsb = ws_base + cur * ws_sz;
        #pragma unroll
        for (int ks = 0; ks < 2; ks++) {
            int kb = ks * 16;
            uint32_t af[2][4], bf[2][4];
            #pragma unroll
            for (int mt = 0; mt < 2; mt++) {
                int row = wm + mt * 16 + a_r;
                int col = kb + a_c;
                ldsm_x4(af[mt], asb + (uint32_t)(row * ASTR + col) * 2);
            }
            #pragma unroll
            for (int p = 0; p < 2; p++) {
                int row = kb + (lane & 15);
                int col = wn + p * 16 + (lane >> 4) * 8;
                ldsm_x4_trans(bf[p], wsb + (uint32_t)(row * BSTR + col) * 2);
            }
            #pragma unroll
            for (int mt = 0; mt < 2; mt++)
                #pragma unroll
                for (int nt = 0; nt < 4; nt++)
                    mma_bf16(acc[mt][nt], af[mt], &bf[nt >> 1][(nt & 1) * 2]);
        }

        if (s < 7) {
            #pragma unroll
            for (int i = 0; i < 2; i++)
                *(uint4*)&As[nxt][a_row[i] * ASTR + a_col[i]] = pa[i];
            *(uint4*)&Ws[nxt][w_row * BSTR + w_col] = pb;
            __syncthreads();
        }
    }

    // ---- epilogue ----
    #pragma unroll
    for (int mt = 0; mt < 2; mt++) {
        int r0 = bm + wm + mt * 16 + (lane >> 2);
        #pragma unroll
        for (int nt = 0; nt < 4; nt++) {
            int cb = bn + wn + nt * 8 + (lane & 3) * 2;
            float b0 = bias[cb], b1 = bias[cb + 1];
            float2 lo = make_float2(acc[mt][nt][0] + b0, acc[mt][nt][1] + b1);
            float2 hi = make_float2(acc[mt][nt][2] + b0, acc[mt][nt][3] + b1);
            if (gelu) {
                lo.x = 0.5f * lo.x * (1.0f + erff(lo.x * 0.70710678118654752f));
                lo.y = 0.5f * lo.y * (1.0f + erff(lo.y * 0.70710678118654752f));
                hi.x = 0.5f * hi.x * (1.0f + erff(hi.x * 0.70710678118654752f));
                hi.y = 0.5f * hi.y * (1.0f + erff(hi.y * 0.70710678118654752f));
            }
            if (C && cb >= cfrom) {
                if (r0 < N)     *(float2*)&C[(size_t)r0 * M + cb] = lo;
                if (r0 + 8 < N) *(float2*)&C[(size_t)(r0 + 8) * M + cb] = hi;
            }
            if (Cb && cb < cbto) {
                __nv_bfloat162 blo = __float22bfloat162_rn(lo);
                __nv_bfloat162 bhi = __float22bfloat162_rn(hi);
                if (r0 < N)     *(__nv_bfloat162*)&Cb[(size_t)r0 * cbs + cb] = blo;
                if (r0 + 8 < N) *(__nv_bfloat162*)&Cb[(size_t)(r0 + 8) * cbs + cb] = bhi;
            }
        }
    }
}

// ---------------- edge attention ----------------
// Qb: bf16 [q|k] rows stride 512 (query side); KVb: bf16 [q|k] rows (kv side);
// Vf: fp32 packed rows stride 768, v at +512.
__global__ void edge_attn(
    const __nv_bfloat16* __restrict__ Qb,
    const __nv_bfloat16* __restrict__ KVb,
    const float* __restrict__ Vf,
    const int* __restrict__ eq, const int* __restrict__ ek,
    int nE, float* __restrict__ num, float* __restrict__ den)
{
    int warp = (int)(((size_t)blockIdx.x * blockDim.x + threadIdx.x) >> 5);
    int lane = threadIdx.x & 31;
    if (warp >= nE) return;
    int s = eq[warp];
    int t = ek[warp];

    uint4 qu = *(const uint4*)&Qb[(size_t)s * 512 + lane * 8];
    uint4 ku = *(const uint4*)&KVb[(size_t)t * 512 + 256 + lane * 8];
    float p = 0.0f;
    {
        const __nv_bfloat162* qp = (const __nv_bfloat162*)&qu;
        const __nv_bfloat162* kp = (const __nv_bfloat162*)&ku;
        #pragma unroll
        for (int i = 0; i < 4; i++) {
            float2 qf = __bfloat1622float2(qp[i]);
            float2 kf = __bfloat1622float2(kp[i]);
            p += qf.x * kf.x + qf.y * kf.y;
        }
    }
    p += __shfl_xor_sync(0xffffffffu, p, 1);
    p += __shfl_xor_sync(0xffffffffu, p, 2);
    float e = __expf(p * 0.17677669529663687f);   // head = lane>>2

    if ((lane & 3) == 0)
        atomicAdd(&den[(size_t)s * NHEAD + (lane >> 2)], e);

    #pragma unroll
    for (int ch = 0; ch < 2; ch++) {
        float ec = __shfl_sync(0xffffffffu, e, 16 * ch + ((lane >> 3) << 2));
        float4 vv = *(const float4*)&Vf[(size_t)t * 768 + 512 + ch * 128 + lane * 4];
        red_add_v4(&num[(size_t)s * 256 + ch * 128 + lane * 4],
                   make_float4(ec * vv.x, ec * vv.y, ec * vv.z, ec * vv.w));
    }
}

// ---------------- y = LN(x + num_p/den_p + num_n/den_n), dual fp32+bf16 out ----------------
__global__ void ln_att(const float* __restrict__ x,
                       const float* __restrict__ np_, const float* __restrict__ dp,
                       const float* __restrict__ nn_, const float* __restrict__ dn,
                       const float* __restrict__ g, const float* __restrict__ b,
                       float* __restrict__ y, __nv_bfloat16* __restrict__ yb, int n)
{
    int row = blockIdx.x * (blockDim.x >> 5) + (threadIdx.x >> 5);
    int lane = threadIdx.x & 31;
    if (row >= n) return;
    float vals[8];
    float s = 0.0f;
    #pragma unroll
    for (int i = 0; i < 8; i++) {
        size_t idx = (size_t)row * 256 + i * 32 + lane;
        float a = x[idx];
        float dpi = dp[(size_t)row * NHEAD + i];
        float dni = dn[(size_t)row * NHEAD + i];
        if (dpi > 0.0f) a += np_[idx] / dpi;
        if (dni > 0.0f) a += nn_[idx] / dni;
        vals[i] = a;
        s += a;
    }
    #pragma unroll
    for (int o = 16; o > 0; o >>= 1) s += __shfl_xor_sync(0xffffffffu, s, o);
    float mean = s * (1.0f / 256.0f);
    float v2 = 0.0f;
    #pragma unroll
    for (int i = 0; i < 8; i++) { float d = vals[i] - mean; v2 += d * d; }
    #pragma unroll
    for (int o = 16; o > 0; o >>= 1) v2 += __shfl_xor_sync(0xffffffffu, v2, o);
    float rstd = rsqrtf(v2 * (1.0f / 256.0f) + 1e-5f);
    #pragma unroll
    for (int i = 0; i < 8; i++) {
        int cidx = i * 32 + lane;
        float out = (vals[i] - mean) * rstd * g[cidx] + b[cidx];
        y[(size_t)row * 256 + cidx] = out;
        yb[(size_t)row * 256 + cidx] = __float2bfloat16(out);
    }
}

// ---------------- y = LN(x + a) ----------------
__global__ void ln_add(const float* __restrict__ x, const float* __restrict__ a,
                       const float* __restrict__ g, const float* __restrict__ b,
                       float* __restrict__ y, int n)
{
    int row = blockIdx.x * (blockDim.x >> 5) + (threadIdx.x >> 5);
    int lane = threadIdx.x & 31;
    if (row >= n) return;
    float vals[8];
    float s = 0.0f;
    #pragma unroll
    for (int i = 0; i < 8; i++) {
        size_t idx = (size_t)row * 256 + i * 32 + lane;
        vals[i] = x[idx] + a[idx];
        s += vals[i];
    }
    #pragma unroll
    for (int o = 16; o > 0; o >>= 1) s += __shfl_xor_sync(0xffffffffu, s, o);
    float mean = s * (1.0f / 256.0f);
    float v2 = 0.0f;
    #pragma unroll
    for (int i = 0; i < 8; i++) { float d = vals[i] - mean; v2 += d * d; }
    #pragma unroll
    for (int o = 16; o > 0; o >>= 1) v2 += __shfl_xor_sync(0xffffffffu, v2, o);
    float rstd = rsqrtf(v2 * (1.0f / 256.0f) + 1e-5f);
    #pragma unroll
    for (int i = 0; i < 8; i++) {
        int cidx = i * 32 + lane;
        y[(size_t)row * 256 + cidx] = (vals[i] - mean) * rstd * g[cidx] + b[cidx];
    }
}

static inline void launch_gemm(const __nv_bfloat16* A, int lda, const __nv_bfloat16* W,
                               const float* bias, float* C, int cfrom,
                               __nv_bfloat16* Cb, int cbto, int cbs,
                               int N, int M, int gelu) {
    dim3 grid(M / BN, (N + BM - 1) / BM);
    tgemm<<<grid, 256>>>(A, lda, W, bias, C, cfrom, Cb, cbto, cbs, N, M, gelu);
}

extern "C" void kernel_launch(void* const* d_in, const int* in_sizes, int n_in,
                              void* d_out, int out_size)
{
    const float* v       = (const float*)d_in[0];
    const float* c       = (const float*)d_in[1];
    const int*   adj_pos = (const int*)d_in[2];
    const int*   adj_neg = (const int*)d_in[3];
    const float* Wq      = (const float*)d_in[4];
    const float* bq      = (const float*)d_in[5];
    const float* Wkv     = (const float*)d_in[6];
    const float* bkv     = (const float*)d_in[7];
    const float* fvw1    = (const float*)d_in[8];
    const float* fvb1    = (const float*)d_in[9];
    const float* fvw2    = (const float*)d_in[10];
    const float* fvb2    = (const float*)d_in[11];
    const float* fcw1    = (const float*)d_in[12];
    const float* fcb1    = (const float*)d_in[13];
    const float* fcw2    = (const float*)d_in[14];
    const float* fcb2    = (const float*)d_in[15];
    const float* lavg    = (const float*)d_in[16];
    const float* lavb    = (const float*)d_in[17];
    const float* lfvg    = (const float*)d_in[18];
    const float* lfvb    = (const float*)d_in[19];
    const float* lacg    = (const float*)d_in[20];
    const float* lacb    = (const float*)d_in[21];
    const float* lfcg    = (const float*)d_in[22];
    const float* lfcb    = (const float*)d_in[23];

    int E = in_sizes[2] / 2;

    float* buf;
    cudaGetSymbolAddress((void**)&buf, g_scratch);

    float* pv    = buf + OFF_PV;
    float* pc    = buf + OFF_PC;
    float* numVp = buf + OFF_NUMVP;
    float* numVn = buf + OFF_NUMVN;
    float* numCp = buf + OFF_NUMCP;
    float* numCn = buf + OFF_NUMCN;
    float* denVp = buf + OFF_DENVP;
    float* denVn = buf + OFF_DENVN;
    float* denCp = buf + OFF_DENCP;
    float* denCn = buf + OFF_DENCN;
    float* v1    = buf + OFF_V1;
    float* c1    = buf + OFF_C1;
    float* tmp   = buf + OFF_TMP;
    float* b768  = buf + OFF_B768;

    __nv_bfloat16* bfb   = (__nv_bfloat16*)(buf + OFF_BF);
    __nv_bfloat16* v_bf  = bfb + B_VBF;
    __nv_bfloat16* c_bf  = bfb + B_CBF;
    __nv_bfloat16* pvb   = bfb + B_PVB;
    __nv_bfloat16* pcb   = bfb + B_PCB;
    __nv_bfloat16* v1b   = bfb + B_V1B;
    __nv_bfloat16* c1b   = bfb + B_C1B;
    __nv_bfloat16* hidb  = bfb + B_HID;
    __nv_bfloat16* wqkvb = bfb + B_WQKV;
    __nv_bfloat16* ffnw  = bfb + B_FFNW;
    __nv_bfloat16* fvw1b = ffnw;
    __nv_bfloat16* fvw2b = ffnw + 65536;
    __nv_bfloat16* fcw1b = ffnw + 131072;
    __nv_bfloat16* fcw2b = ffnw + 196608;

    float* out_v = (float*)d_out;
    float* out_c = out_v + (size_t)NVAR * DIM;

    // ---- conversions ----
    cvt_f2b4<<<(NVAR * 64 + 255) / 256, 256>>>(v, v_bf, NVAR * 64);
    cvt_f2b4<<<(NCLS * 64 + 255) / 256, 256>>>(c, c_bf, NCLS * 64);
    cvt_w4<<<256, 256>>>(fvw1, fvw2, fcw1, fcw2, ffnw);
    build_wqkv<<<768, 256>>>(Wq, Wkv, wqkvb);
    build_bias768<<<3, 256>>>(bq, bkv, b768);

    cudaMemsetAsync(numVp, 0, (size_t)(OFF_V1 - OFF_NUMVP) * sizeof(float), 0);

    // ---- fused projections: bf16 [q|k] + fp32 v-part ----
    launch_gemm(v_bf, 256, wqkvb, b768, pv, 512, pvb, 512, 512, NVAR, 768, 0);
    launch_gemm(c_bf, 256, wqkvb, b768, pc, 512, pcb, 512, 512, NCLS, 768, 0);

    int eblocks = (E * 32 + 255) / 256;

    edge_attn<<<eblocks, 256>>>(pvb, pcb, pc, adj_pos + E, adj_pos, E, numVp, denVp);
    edge_attn<<<eblocks, 256>>>(pcb, pvb, pv, adj_pos, adj_pos + E, E, numCp, denCp);
    edge_attn<<<eblocks, 256>>>(pvb, pcb, pc, adj_neg + E, adj_neg, E, numVn, denVn);
    edge_attn<<<eblocks, 256>>>(pcb, pvb, pv, adj_neg, adj_neg + E, E, numCn, denCn);

    ln_att<<<(NVAR + 7) / 8, 256>>>(v, numVp, denVp, numVn, denVn, lavg, lavb, v1, v1b, NVAR);
    ln_att<<<(NCLS + 7) / 8, 256>>>(c, numCp, denCp, numCn, denCn, lacg, lacb, c1, c1b, NCLS);

    // FFN v
    launch_gemm(v1b, 256, fvw1b, fvb1, nullptr, 1 << 30, hidb, 256, 256, NVAR, 256, 1);
    launch_gemm(hidb, 256, fvw2b, fvb2, tmp, 0, nullptr, 0, 0, NVAR, 256, 0);
    ln_add<<<(NVAR + 7) / 8, 256>>>(v1, tmp, lfvg, lfvb, out_v, NVAR);

    // FFN c
    launch_gemm(c1b, 256, fcw1b, fcb1, nullptr, 1 << 30, hidb, 256, 256, NCLS, 256, 1);
    launch_gemm(hidb, 256, fcw2b, fcb2, tmp, 0, nullptr, 0, 0, NCLS, 256, 0);
    ln_add<<<(NCLS + 7) / 8, 256>>>(c1, tmp, lfcg, lfcb, out_c, NCLS);
}

// round 8
// speedup vs baseline: 1.1827x; 1.1203x over previous
#include <cuda_runtime.h>
#include <cuda_bf16.h>
#include <math.h>
#include <stdint.h>

#define NVAR 30000
#define NCLS 60000
#define DIM 256
#define NHEAD 8

// ---------------- scratch layout (float units) ----------------
#define OFF_PV     0ull            // 30000*768 fp32 (only v-part cols 512..767 written)
#define OFF_PC     23040000ull     // 60000*768 fp32
#define OFF_NUMVP  69120000ull
#define OFF_NUMVN  76800000ull
#define OFF_NUMCP  84480000ull
#define OFF_NUMCN  99840000ull
#define OFF_DENVP  115200000ull
#define OFF_DENVN  115440000ull
#define OFF_DENCP  115680000ull
#define OFF_DENCN  116160000ull
#define OFF_V1     116640000ull    // 30000*256 fp32
#define OFF_C1     124320000ull    // 60000*256 fp32
#define OFF_TMP    139680000ull    // 60000*256 fp32
#define OFF_B768   155040000ull    // 1024 floats
#define OFF_BF     155041024ull    // bf16 area
// bf16-element offsets within BF area:
#define B_VBF   0ull               // 30000*256
#define B_CBF   7680000ull         // 60000*256
#define B_PVB   23040000ull        // 30000*512  [q|k] bf16
#define B_PCB   38400000ull        // 60000*512
#define B_V1B   69120000ull        // 30000*256
#define B_C1B   76800000ull        // 60000*256
#define B_HID   92160000ull        // 60000*256
#define B_WQKV  107520000ull       // 256*768
#define B_FFNW  107716608ull       // 4*65536
#define SCRATCH_TOTAL 209030400ull

__device__ float g_scratch[SCRATCH_TOTAL];

// ---------------- helpers ----------------
__device__ __forceinline__ void ldsm_x4(uint32_t* r, uint32_t saddr) {
    asm volatile("ldmatrix.sync.aligned.m8n8.x4.shared.b16 {%0,%1,%2,%3}, [%4];"
                 : "=r"(r[0]), "=r"(r[1]), "=r"(r[2]), "=r"(r[3]) : "r"(saddr));
}
__device__ __forceinline__ void ldsm_x4_trans(uint32_t* r, uint32_t saddr) {
    asm volatile("ldmatrix.sync.aligned.m8n8.x4.trans.shared.b16 {%0,%1,%2,%3}, [%4];"
                 : "=r"(r[0]), "=r"(r[1]), "=r"(r[2]), "=r"(r[3]) : "r"(saddr));
}
__device__ __forceinline__ void mma_bf16(float* d, const uint32_t* a, const uint32_t* b) {
    asm volatile(
        "mma.sync.aligned.m16n8k16.row.col.f32.bf16.bf16.f32 "
        "{%0,%1,%2,%3}, {%4,%5,%6,%7}, {%8,%9}, {%0,%1,%2,%3};"
        : "+f"(d[0]), "+f"(d[1]), "+f"(d[2]), "+f"(d[3])
        : "r"(a[0]), "r"(a[1]), "r"(a[2]), "r"(a[3]),
          "r"(b[0]), "r"(b[1]));
}
__device__ __forceinline__ void red_add_v4(float* addr, float4 v) {
    asm volatile("red.global.add.v4.f32 [%0], {%1,%2,%3,%4};"
                 :: "l"(addr), "f"(v.x), "f"(v.y), "f"(v.z), "f"(v.w) : "memory");
}

// ---------------- conversion kernels ----------------
__global__ void cvt_f2b4(const float* __restrict__ s, __nv_bfloat16* __restrict__ d, int n4) {
    int i = blockIdx.x * blockDim.x + threadIdx.x;
    if (i >= n4) return;
    float4 t = ((const float4*)s)[i];
    __nv_bfloat162 lo = __float22bfloat162_rn(make_float2(t.x, t.y));
    __nv_bfloat162 hi = __float22bfloat162_rn(make_float2(t.z, t.w));
    ((uint2*)d)[i] = make_uint2(*(uint32_t*)&lo, *(uint32_t*)&hi);
}
__global__ void cvt_w4(const float* __restrict__ w1, const float* __restrict__ w2,
                       const float* __restrict__ w3, const float* __restrict__ w4,
                       __nv_bfloat16* __restrict__ dst) {
    int i = blockIdx.x * blockDim.x + threadIdx.x;
    if (i >= 65536) return;
    int which = i >> 14;
    int j = i & 16383;
    const float* src = (which == 0) ? w1 : (which == 1) ? w2 : (which == 2) ? w3 : w4;
    float4 t = ((const float4*)src)[j];
    __nv_bfloat162 lo = __float22bfloat162_rn(make_float2(t.x, t.y));
    __nv_bfloat162 hi = __float22bfloat162_rn(make_float2(t.z, t.w));
    ((uint2*)(dst + (size_t)which * 65536))[j] = make_uint2(*(uint32_t*)&lo, *(uint32_t*)&hi);
}
__global__ void build_wqkv(const float* __restrict__ Wq, const float* __restrict__ Wkv,
                           __nv_bfloat16* __restrict__ dst) {
    int i = blockIdx.x * blockDim.x + threadIdx.x;
    if (i >= 256 * 768) return;
    int k = i / 768, j = i % 768;
    float val = (j < 256) ? Wq[k * 256 + j] : Wkv[k * 512 + (j - 256)];
    dst[i] = __float2bfloat16(val);
}
__global__ void build_bias768(const float* __restrict__ bq, const float* __restrict__ bkv,
                              float* __restrict__ dst) {
    int j = blockIdx.x * blockDim.x + threadIdx.x;
    if (j < 768) dst[j] = (j < 256) ? bq[j] : bkv[j - 256];
}

// ---------------- bf16 tensor-core GEMM, 128x128 tile, double-buffered ----------------
#define BM 128
#define BN 128
#define BK 32
#define ASTR 40
#define BSTR 136

__global__ __launch_bounds__(256, 2) void tgemm(
    const __nv_bfloat16* __restrict__ A, int lda,
    const __nv_bfloat16* __restrict__ W,
    const float* __restrict__ bias,
    float* __restrict__ C, int cfrom,
    __nv_bfloat16* __restrict__ Cb, int cbto, int cbs,
    int N, int M, int gelu)
{
    __shared__ __nv_bfloat16 As[2][BM * ASTR];
    __shared__ __nv_bfloat16 Ws[2][BK * BSTR];

    int tid = threadIdx.x;
    int lane = tid & 31;
    int warp = tid >> 5;
    int wm = (warp & 3) * 32;
    int wn = (warp >> 2) * 64;
    int bm = blockIdx.y * BM;
    int bn = blockIdx.x * BN;

    uint32_t as_base = (uint32_t)__cvta_generic_to_shared(&As[0][0]);
    uint32_t ws_base = (uint32_t)__cvta_generic_to_shared(&Ws[0][0]);
    const uint32_t as_sz = BM * ASTR * 2;
    const uint32_t ws_sz = BK * BSTR * 2;

    // A: 512 granules (128r x 4c of 8 bf16); 2 per thread
    int a_row[2], a_col[2];
    // W: 512 granules (32r x 16c of 8 bf16); 2 per thread
    int w_row[2], w_col[2];
    #pragma unroll
    for (int i = 0; i < 2; i++) {
        int g = tid + i * 256;
        a_row[i] = (tid * 2 + i) >> 2;
        a_col[i] = ((tid * 2 + i) & 3) * 8;
        w_row[i] = g >> 4;
        w_col[i] = (g & 15) * 8;
    }

    uint4 pa[2], pb[2];
    const uint4 zero4 = make_uint4(0, 0, 0, 0);

    float acc[2][8][4];
    #pragma unroll
    for (int mt = 0; mt < 2; mt++)
        #pragma unroll
        for (int nt = 0; nt < 8; nt++)
            #pragma unroll
            for (int i = 0; i < 4; i++) acc[mt][nt][i] = 0.0f;

    int a_r = lane & 15;
    int a_c = (lane >> 4) * 8;

    // ---- slab 0 -> buffer 0 ----
    #pragma unroll
    for (int i = 0; i < 2; i++) {
        int gr = bm + a_row[i];
        pa[i] = (gr < N) ? *(const uint4*)&A[(size_t)gr * lda + a_col[i]] : zero4;
        pb[i] = *(const uint4*)&W[(size_t)w_row[i] * M + bn + w_col[i]];
    }
    #pragma unroll
    for (int i = 0; i < 2; i++) {
        *(uint4*)&As[0][a_row[i] * ASTR + a_col[i]] = pa[i];
        *(uint4*)&Ws[0][w_row[i] * BSTR + w_col[i]] = pb[i];
    }
    __syncthreads();

    for (int s = 0; s < 8; s++) {
        int cur = s & 1, nxt = cur ^ 1;
        if (s < 7) {
            int k0 = (s + 1) * BK;
            #pragma unroll
            for (int i = 0; i < 2; i++) {
                int gr = bm + a_row[i];
                pa[i] = (gr < N) ? *(const uint4*)&A[(size_t)gr * lda + k0 + a_col[i]] : zero4;
                pb[i] = *(const uint4*)&W[(size_t)(k0 + w_row[i]) * M + bn + w_col[i]];
            }
        }

        uint32_t asb = as_base + cur * as_sz;
        uint32_t wsb = ws_base + cur * ws_sz;
        #pragma unroll
        for (int ks = 0; ks < 2; ks++) {
            int kb = ks * 16;
            uint32_t af[2][4], bf[4][4];
            #pragma unroll
            for (int mt = 0; mt < 2; mt++) {
                int row = wm + mt * 16 + a_r;
                int col = kb + a_c;
                ldsm_x4(af[mt], asb + (uint32_t)(row * ASTR + col) * 2);
            }
            #pragma unroll
            for (int p = 0; p < 4; p++) {
                int row = kb + (lane & 15);
                int col = wn + p * 16 + (lane >> 4) * 8;
                ldsm_x4_trans(bf[p], wsb + (uint32_t)(row * BSTR + col) * 2);
            }
            #pragma unroll
            for (int mt = 0; mt < 2; mt++)
                #pragma unroll
                for (int nt = 0; nt < 8; nt++)
                    mma_bf16(acc[mt][nt], af[mt], &bf[nt >> 1][(nt & 1) * 2]);
        }

        if (s < 7) {
            #pragma unroll
            for (int i = 0; i < 2; i++) {
                *(uint4*)&As[nxt][a_row[i] * ASTR + a_col[i]] = pa[i];
                *(uint4*)&Ws[nxt][w_row[i] * BSTR + w_col[i]] = pb[i];
            }
            __syncthreads();
        }
    }

    // ---- epilogue ----
    #pragma unroll
    for (int mt = 0; mt < 2; mt++) {
        int r0 = bm + wm + mt * 16 + (lane >> 2);
        #pragma unroll
        for (int nt = 0; nt < 8; nt++) {
            int cb = bn + wn + nt * 8 + (lane & 3) * 2;
            float b0 = bias[cb], b1 = bias[cb + 1];
            float2 lo = make_float2(acc[mt][nt][0] + b0, acc[mt][nt][1] + b1);
            float2 hi = make_float2(acc[mt][nt][2] + b0, acc[mt][nt][3] + b1);
            if (gelu) {
                lo.x = 0.5f * lo.x * (1.0f + erff(lo.x * 0.70710678118654752f));
                lo.y = 0.5f * lo.y * (1.0f + erff(lo.y * 0.70710678118654752f));
                hi.x = 0.5f * hi.x * (1.0f + erff(hi.x * 0.70710678118654752f));
                hi.y = 0.5f * hi.y * (1.0f + erff(hi.y * 0.70710678118654752f));
            }
            if (C && cb >= cfrom) {
                if (r0 < N)     *(float2*)&C[(size_t)r0 * M + cb] = lo;
                if (r0 + 8 < N) *(float2*)&C[(size_t)(r0 + 8) * M + cb] = hi;
            }
            if (Cb && cb < cbto) {
                __nv_bfloat162 blo = __float22bfloat162_rn(lo);
                __nv_bfloat162 bhi = __float22bfloat162_rn(hi);
                if (r0 < N)     *(__nv_bfloat162*)&Cb[(size_t)r0 * cbs + cb] = blo;
                if (r0 + 8 < N) *(__nv_bfloat162*)&Cb[(size_t)(r0 + 8) * cbs + cb] = bhi;
            }
        }
    }
}

// ---------------- edge attention ----------------
__global__ void edge_attn(
    const __nv_bfloat16* __restrict__ Qb,
    const __nv_bfloat16* __restrict__ KVb,
    const float* __restrict__ Vf,
    const int* __restrict__ eq, const int* __restrict__ ek,
    int nE, float* __restrict__ num, float* __restrict__ den)
{
    int warp = (int)(((size_t)blockIdx.x * blockDim.x + threadIdx.x) >> 5);
    int lane = threadIdx.x & 31;
    if (warp >= nE) return;
    int s = eq[warp];
    int t = ek[warp];

    uint4 qu = *(const uint4*)&Qb[(size_t)s * 512 + lane * 8];
    uint4 ku = *(const uint4*)&KVb[(size_t)t * 512 + 256 + lane * 8];
    float p = 0.0f;
    {
        const __nv_bfloat162* qp = (const __nv_bfloat162*)&qu;
        const __nv_bfloat162* kp = (const __nv_bfloat162*)&ku;
        #pragma unroll
        for (int i = 0; i < 4; i++) {
            float2 qf = __bfloat1622float2(qp[i]);
            float2 kf = __bfloat1622float2(kp[i]);
            p += qf.x * kf.x + qf.y * kf.y;
        }
    }
    p += __shfl_xor_sync(0xffffffffu, p, 1);
    p += __shfl_xor_sync(0xffffffffu, p, 2);
    float e = __expf(p * 0.17677669529663687f);

    if ((lane & 3) == 0)
        atomicAdd(&den[(size_t)s * NHEAD + (lane >> 2)], e);

    #pragma unroll
    for (int ch = 0; ch < 2; ch++) {
        float ec = __shfl_sync(0xffffffffu, e, 16 * ch + ((lane >> 3) << 2));
        float4 vv = *(const float4*)&Vf[(size_t)t * 768 + 512 + ch * 128 + lane * 4];
        red_add_v4(&num[(size_t)s * 256 + ch * 128 + lane * 4],
                   make_float4(ec * vv.x, ec * vv.y, ec * vv.z, ec * vv.w));
    }
}

// ---------------- y = LN(x + num_p/den_p + num_n/den_n), dual fp32+bf16 out ----------------
__global__ void ln_att(const float* __restrict__ x,
                       const float* __restrict__ np_, const float* __restrict__ dp,
                       const float* __restrict__ nn_, const float* __restrict__ dn,
                       const float* __restrict__ g, const float* __restrict__ b,
                       float* __restrict__ y, __nv_bfloat16* __restrict__ yb, int n)
{
    int row = blockIdx.x * (blockDim.x >> 5) + (threadIdx.x >> 5);
    int lane = threadIdx.x & 31;
    if (row >= n) return;
    float vals[8];
    float s = 0.0f;
    #pragma unroll
    for (int i = 0; i < 8; i++) {
        size_t idx = (size_t)row * 256 + i * 32 + lane;
        float a = x[idx];
        float dpi = dp[(size_t)row * NHEAD + i];
        float dni = dn[(size_t)row * NHEAD + i];
        if (dpi > 0.0f) a += np_[idx] / dpi;
        if (dni > 0.0f) a += nn_[idx] / dni;
        vals[i] = a;
        s += a;
    }
    #pragma unroll
    for (int o = 16; o > 0; o >>= 1) s += __shfl_xor_sync(0xffffffffu, s, o);
    float mean = s * (1.0f / 256.0f);
    float v2 = 0.0f;
    #pragma unroll
    for (int i = 0; i < 8; i++) { float d = vals[i] - mean; v2 += d * d; }
    #pragma unroll
    for (int o = 16; o > 0; o >>= 1) v2 += __shfl_xor_sync(0xffffffffu, v2, o);
    float rstd = rsqrtf(v2 * (1.0f / 256.0f) + 1e-5f);
    #pragma unroll
    for (int i = 0; i < 8; i++) {
        int cidx = i * 32 + lane;
        float out = (vals[i] - mean) * rstd * g[cidx] + b[cidx];
        y[(size_t)row * 256 + cidx] = out;
        yb[(size_t)row * 256 + cidx] = __float2bfloat16(out);
    }
}

// ---------------- y = LN(x + a) ----------------
__global__ void ln_add(const float* __restrict__ x, const float* __restrict__ a,
                       const float* __restrict__ g, const float* __restrict__ b,
                       float* __restrict__ y, int n)
{
    int row = blockIdx.x * (blockDim.x >> 5) + (threadIdx.x >> 5);
    int lane = threadIdx.x & 31;
    if (row >= n) return;
    float vals[8];
    float s = 0.0f;
    #pragma unroll
    for (int i = 0; i < 8; i++) {
        size_t idx = (size_t)row * 256 + i * 32 + lane;
        vals[i] = x[idx] + a[idx];
        s += vals[i];
    }
    #pragma unroll
    for (int o = 16; o > 0; o >>= 1) s += __shfl_xor_sync(0xffffffffu, s, o);
    float mean = s * (1.0f / 256.0f);
    float v2 = 0.0f;
    #pragma unroll
    for (int i = 0; i < 8; i++) { float d = vals[i] - mean; v2 += d * d; }
    #pragma unroll
    for (int o = 16; o > 0; o >>= 1) v2 += __shfl_xor_sync(0xffffffffu, v2, o);
    float rstd = rsqrtf(v2 * (1.0f / 256.0f) + 1e-5f);
    #pragma unroll
    for (int i = 0; i < 8; i++) {
        int cidx = i * 32 + lane;
        y[(size_t)row * 256 + cidx] = (vals[i] - mean) * rstd * g[cidx] + b[cidx];
    }
}

static inline void launch_gemm(const __nv_bfloat16* A, int lda, const __nv_bfloat16* W,
                               const float* bias, float* C, int cfrom,
                               __nv_bfloat16* Cb, int cbto, int cbs,
                               int N, int M, int gelu) {
    dim3 grid(M / BN, (N + BM - 1) / BM);
    tgemm<<<grid, 256>>>(A, lda, W, bias, C, cfrom, Cb, cbto, cbs, N, M, gelu);
}

extern "C" void kernel_launch(void* const* d_in, const int* in_sizes, int n_in,
                              void* d_out, int out_size)
{
    const float* v       = (const float*)d_in[0];
    const float* c       = (const float*)d_in[1];
    const int*   adj_pos = (const int*)d_in[2];
    const int*   adj_neg = (const int*)d_in[3];
    const float* Wq      = (const float*)d_in[4];
    const float* bq      = (const float*)d_in[5];
    const float* Wkv     = (const float*)d_in[6];
    const float* bkv     = (const float*)d_in[7];
    const float* fvw1    = (const float*)d_in[8];
    const float* fvb1    = (const float*)d_in[9];
    const float* fvw2    = (const float*)d_in[10];
    const float* fvb2    = (const float*)d_in[11];
    const float* fcw1    = (const float*)d_in[12];
    const float* fcb1    = (const float*)d_in[13];
    const float* fcw2    = (const float*)d_in[14];
    const float* fcb2    = (const float*)d_in[15];
    const float* lavg    = (const float*)d_in[16];
    const float* lavb    = (const float*)d_in[17];
    const float* lfvg    = (const float*)d_in[18];
    const float* lfvb    = (const float*)d_in[19];
    const float* lacg    = (const float*)d_in[20];
    const float* lacb    = (const float*)d_in[21];
    const float* lfcg    = (const float*)d_in[22];
    const float* lfcb    = (const float*)d_in[23];

    int E = in_sizes[2] / 2;

    float* buf;
    cudaGetSymbolAddress((void**)&buf, g_scratch);

    float* pv    = buf + OFF_PV;
    float* pc    = buf + OFF_PC;
    float* numVp = buf + OFF_NUMVP;
    float* numVn = buf + OFF_NUMVN;
    float* numCp = buf + OFF_NUMCP;
    float* numCn = buf + OFF_NUMCN;
    float* denVp = buf + OFF_DENVP;
    float* denVn = buf + OFF_DENVN;
    float* denCp = buf + OFF_DENCP;
    float* denCn = buf + OFF_DENCN;
    float* v1    = buf + OFF_V1;
    float* c1    = buf + OFF_C1;
    float* tmp   = buf + OFF_TMP;
    float* b768  = buf + OFF_B768;

    __nv_bfloat16* bfb   = (__nv_bfloat16*)(buf + OFF_BF);
    __nv_bfloat16* v_bf  = bfb + B_VBF;
    __nv_bfloat16* c_bf  = bfb + B_CBF;
    __nv_bfloat16* pvb   = bfb + B_PVB;
    __nv_bfloat16* pcb   = bfb + B_PCB;
    __nv_bfloat16* v1b   = bfb + B_V1B;
    __nv_bfloat16* c1b   = bfb + B_C1B;
    __nv_bfloat16* hidb  = bfb + B_HID;
    __nv_bfloat16* wqkvb = bfb + B_WQKV;
    __nv_bfloat16* ffnw  = bfb + B_FFNW;
    __nv_bfloat16* fvw1b = ffnw;
    __nv_bfloat16* fvw2b = ffnw + 65536;
    __nv_bfloat16* fcw1b = ffnw + 131072;
    __nv_bfloat16* fcw2b = ffnw + 196608;

    float* out_v = (float*)d_out;
    float* out_c = out_v + (size_t)NVAR * DIM;

    // ---- conversions ----
    cvt_f2b4<<<(NVAR * 64 + 255) / 256, 256>>>(v, v_bf, NVAR * 64);
    cvt_f2b4<<<(NCLS * 64 + 255) / 256, 256>>>(c, c_bf, NCLS * 64);
    cvt_w4<<<256, 256>>>(fvw1, fvw2, fcw1, fcw2, ffnw);
    build_wqkv<<<768, 256>>>(Wq, Wkv, wqkvb);
    build_bias768<<<3, 256>>>(bq, bkv, b768);

    cudaMemsetAsync(numVp, 0, (size_t)(OFF_V1 - OFF_NUMVP) * sizeof(float), 0);

    // ---- fused projections: bf16 [q|k] + fp32 v-part ----
    launch_gemm(v_bf, 256, wqkvb, b768, pv, 512, pvb, 512, 512, NVAR, 768, 0);
    launch_gemm(c_bf, 256, wqkvb, b768, pc, 512, pcb, 512, 512, NCLS, 768, 0);

    int eblocks = (E * 32 + 255) / 256;

    edge_attn<<<eblocks, 256>>>(pvb, pcb, pc, adj_pos + E, adj_pos, E, numVp, denVp);
    edge_attn<<<eblocks, 256>>>(pcb, pvb, pv, adj_pos, adj_pos + E, E, numCp, denCp);
    edge_attn<<<eblocks, 256>>>(pvb, pcb, pc, adj_neg + E, adj_neg, E, numVn, denVn);
    edge_attn<<<eblocks, 256>>>(pcb, pvb, pv, adj_neg, adj_neg + E, E, numCn, denCn);

    ln_att<<<(NVAR + 7) / 8, 256>>>(v, numVp, denVp, numVn, denVn, lavg, lavb, v1, v1b, NVAR);
    ln_att<<<(NCLS + 7) / 8, 256>>>(c, numCp, denCp, numCn, denCn, lacg, lacb, c1, c1b, NCLS);

    // FFN v
    launch_gemm(v1b, 256, fvw1b, fvb1, nullptr, 1 << 30, hidb, 256, 256, NVAR, 256, 1);
    launch_gemm(hidb, 256, fvw2b, fvb2, tmp, 0, nullptr, 0, 0, NVAR, 256, 0);
    ln_add<<<(NVAR + 7) / 8, 256>>>(v1, tmp, lfvg, lfvb, out_v, NVAR);

    // FFN c
    launch_gemm(c1b, 256, fcw1b, fcb1, nullptr, 1 << 30, hidb, 256, 256, NCLS, 256, 1);
    launch_gemm(hidb, 256, fcw2b, fcb2, tmp, 0, nullptr, 0, 0, NCLS, 256, 0);
    ln_add<<<(NCLS + 7) / 8, 256>>>(c1, tmp, lfcg, lfcb, out_c, NCLS);
}